// round 2
// baseline (speedup 1.0000x reference)
#include <cuda_runtime.h>
#include <cuda_bf16.h>
#include <math.h>

// ---------------- device scratch (no allocations allowed) ----------------
__device__ float g_xmean[64];
__device__ float g_attn[64 * 64];
__device__ float g_p1[32 * 512];   // after conv1+pool
__device__ float g_p2[16 * 256];   // after conv2+pool

// ---------------- K1: xmean[c] = mean_l x[0,c,l] ----------------
__global__ void k_xmean(const float* __restrict__ x) {
    int c = blockIdx.x;
    int tid = threadIdx.x;
    const float* xr = x + c * 1024;
    float s = 0.f;
    for (int i = tid; i < 1024; i += 256) s += xr[i];
    __shared__ float red[8];
    #pragma unroll
    for (int o = 16; o > 0; o >>= 1) s += __shfl_xor_sync(0xffffffffu, s, o);
    if ((tid & 31) == 0) red[tid >> 5] = s;
    __syncthreads();
    if (tid < 8) {
        s = red[tid];
        #pragma unroll
        for (int o = 4; o > 0; o >>= 1) s += __shfl_xor_sync(0xffu, s, o);
        if (tid == 0) g_xmean[c] = s * (1.0f / 1024.0f);
    }
}

// ---------------- K2: per-net MLP -> attn rows ----------------
// block i: att = xmean * topo_map[i,:]; h = relu(att @ W1[i]^T); attn[i,:] = sigmoid(h @ W2[i]^T)
__global__ void k_attn(const float* __restrict__ topo,
                       const float* __restrict__ W1,
                       const float* __restrict__ W2) {
    __shared__ float att[64];
    __shared__ float hbuf[128];
    __shared__ float wbuf[128 * 65];   // padded to kill bank conflicts
    int i = blockIdx.x, t = threadIdx.x;

    if (t < 64) att[t] = g_xmean[t] * topo[i * 64 + t];

    // stage W1[i] (128x64) into smem, padded stride 65
    const float* W1i = W1 + i * 8192;
    for (int j = t; j < 8192; j += 128) {
        int h = j >> 6, k = j & 63;
        wbuf[h * 65 + k] = W1i[j];
    }
    __syncthreads();

    {
        float s = 0.f;
        const float* wr = &wbuf[t * 65];
        #pragma unroll 16
        for (int k = 0; k < 64; k++) s += att[k] * wr[k];
        hbuf[t] = fmaxf(s, 0.f);
    }
    __syncthreads();

    // stage W2[i] (64x128) into smem, padded stride 129 (fits: 64*129 <= 128*65)
    const float* W2i = W2 + i * 8192;
    for (int j = t; j < 8192; j += 128) {
        int o = j >> 7, h = j & 127;
        wbuf[o * 129 + h] = W2i[j];
    }
    __syncthreads();

    if (t < 64) {
        float s = 0.f;
        const float* wr = &wbuf[t * 129];
        #pragma unroll 16
        for (int h = 0; h < 128; h++) s += hbuf[h] * wr[h];
        g_attn[i * 64 + t] = 1.0f / (1.0f + __expf(-s));
    }
}

// ---------------- K3: y = attn @ x fused with conv1 + relu + pool ----------------
// 32 blocks, tile of 32 output positions each. Halo of 2 each side (conv pad=2).
__global__ void k_y_conv1(const float* __restrict__ x,
                          const float* __restrict__ c1_w,
                          const float* __restrict__ c1_b) {
    __shared__ float attn_s[64 * 64];
    __shared__ float xs[64 * 36];
    __shared__ float ys[64 * 36];
    int tile = blockIdx.x, tid = threadIdx.x;
    int l0 = tile * 32 - 2;

    for (int j = tid; j < 4096; j += 256) attn_s[j] = g_attn[j];
    for (int j = tid; j < 64 * 36; j += 256) {
        int k = j / 36, jj = j - k * 36;
        int gl = l0 + jj;
        xs[j] = (gl >= 0 && gl < 1024) ? x[k * 1024 + gl] : 0.f;
    }
    __syncthreads();

    // y tile: ys[c][j] = sum_k attn[c,k] * xs[k][j]
    for (int idx = tid; idx < 64 * 36; idx += 256) {
        int c = idx / 36, j = idx - c * 36;
        const float* ar = &attn_s[c * 64];
        float s = 0.f;
        #pragma unroll 8
        for (int k = 0; k < 64; k++) s += ar[k] * xs[k * 36 + j];
        ys[idx] = s;
    }
    __syncthreads();

    // conv1 (32 out-ch) + relu + maxpool2 -> 16 pooled positions per tile
    for (int idx = tid; idx < 512; idx += 256) {
        int o = idx >> 4, p = idx & 15;
        int l = 2 * p;  // local pre-pool position (0..31), pair (l, l+1)
        float z0 = c1_b[o], z1 = z0;
        const float* wo = c1_w + o * 320;
        for (int c = 0; c < 64; c++) {
            const float* yr = &ys[c * 36 + l];
            const float* wc = wo + c * 5;
            #pragma unroll
            for (int dt = 0; dt < 5; dt++) {
                float w = wc[dt];
                z0 += w * yr[dt];
                z1 += w * yr[dt + 1];
            }
        }
        float v = fmaxf(fmaxf(z0, 0.f), fmaxf(z1, 0.f));
        g_p1[o * 512 + tile * 16 + p] = v;
    }
}

// ---------------- K4: conv2 + relu + pool (32,512)->(16,256), grid-parallel ----------------
__global__ void k_conv2(const float* __restrict__ c2_w,
                        const float* __restrict__ c2_b) {
    int idx = blockIdx.x * 256 + threadIdx.x;   // 16*256 = 4096 outputs
    int o = idx >> 8, p = idx & 255;
    int l = 2 * p;
    float z0 = c2_b[o], z1 = z0;
    const float* wo = c2_w + o * 160;
    for (int c = 0; c < 32; c++) {
        const float* pr = &g_p1[c * 512];
        const float* wc = wo + c * 5;
        #pragma unroll
        for (int dt = 0; dt < 5; dt++) {
            int i0 = l + dt - 2;
            int i1 = i0 + 1;
            float w = wc[dt];
            if ((unsigned)i0 < 512u) z0 += w * pr[i0];
            if ((unsigned)i1 < 512u) z1 += w * pr[i1];
        }
    }
    g_p2[o * 256 + p] = fmaxf(fmaxf(z0, 0.f), fmaxf(z1, 0.f));
}

// ---------------- K5: conv3..conv6 + final linear ----------------
__global__ void k_tail(const float* __restrict__ c3_w, const float* __restrict__ c3_b,
                       const float* __restrict__ c4_w, const float* __restrict__ c4_b,
                       const float* __restrict__ c5_w, const float* __restrict__ c5_b,
                       const float* __restrict__ c6_w, const float* __restrict__ c6_b,
                       const float* __restrict__ out_w, const float* __restrict__ out_b,
                       float* __restrict__ out) {
    __shared__ float s2[16 * 256];
    __shared__ float s3[8 * 128];
    __shared__ float s4[4 * 64];
    __shared__ float s5[2 * 32];
    __shared__ float s6[16];
    int tid = threadIdx.x;

    for (int j = tid; j < 4096; j += 512) s2[j] = g_p2[j];
    __syncthreads();

    // conv3: (16,256)->(8,128)
    for (int idx = tid; idx < 1024; idx += 512) {
        int o = idx >> 7, p = idx & 127;
        int l = 2 * p;
        float z0 = c3_b[o], z1 = z0;
        for (int c = 0; c < 16; c++) {
            const float* pr = &s2[c * 256];
            const float* wc = c3_w + o * 80 + c * 5;
            #pragma unroll
            for (int dt = 0; dt < 5; dt++) {
                int i0 = l + dt - 2, i1 = i0 + 1;
                float w = wc[dt];
                if ((unsigned)i0 < 256u) z0 += w * pr[i0];
                if ((unsigned)i1 < 256u) z1 += w * pr[i1];
            }
        }
        s3[o * 128 + p] = fmaxf(fmaxf(z0, 0.f), fmaxf(z1, 0.f));
    }
    __syncthreads();

    // conv4: (8,128)->(4,64)
    if (tid < 256) {
        int o = tid >> 6, p = tid & 63;
        int l = 2 * p;
        float z0 = c4_b[o], z1 = z0;
        for (int c = 0; c < 8; c++) {
            const float* pr = &s3[c * 128];
            const float* wc = c4_w + o * 40 + c * 5;
            #pragma unroll
            for (int dt = 0; dt < 5; dt++) {
                int i0 = l + dt - 2, i1 = i0 + 1;
                float w = wc[dt];
                if ((unsigned)i0 < 128u) z0 += w * pr[i0];
                if ((unsigned)i1 < 128u) z1 += w * pr[i1];
            }
        }
        s4[o * 64 + p] = fmaxf(fmaxf(z0, 0.f), fmaxf(z1, 0.f));
    }
    __syncthreads();

    // conv5: (4,64)->(2,32)
    if (tid < 64) {
        int o = tid >> 5, p = tid & 31;
        int l = 2 * p;
        float z0 = c5_b[o], z1 = z0;
        for (int c = 0; c < 4; c++) {
            const float* pr = &s4[c * 64];
            const float* wc = c5_w + o * 20 + c * 5;
            #pragma unroll
            for (int dt = 0; dt < 5; dt++) {
                int i0 = l + dt - 2, i1 = i0 + 1;
                float w = wc[dt];
                if ((unsigned)i0 < 64u) z0 += w * pr[i0];
                if ((unsigned)i1 < 64u) z1 += w * pr[i1];
            }
        }
        s5[o * 32 + p] = fmaxf(fmaxf(z0, 0.f), fmaxf(z1, 0.f));
    }
    __syncthreads();

    // conv6: (2,32)->(1,16)
    if (tid < 16) {
        int p = tid;
        int l = 2 * p;
        float z0 = c6_b[0], z1 = z0;
        for (int c = 0; c < 2; c++) {
            const float* pr = &s5[c * 32];
            const float* wc = c6_w + c * 5;
            #pragma unroll
            for (int dt = 0; dt < 5; dt++) {
                int i0 = l + dt - 2, i1 = i0 + 1;
                float w = wc[dt];
                if ((unsigned)i0 < 32u) z0 += w * pr[i0];
                if ((unsigned)i1 < 32u) z1 += w * pr[i1];
            }
        }
        s6[p] = fmaxf(fmaxf(z0, 0.f), fmaxf(z1, 0.f));
    }
    __syncthreads();

    if (tid == 0) {
        float s = out_b[0];
        #pragma unroll
        for (int j = 0; j < 16; j++) s += s6[j] * out_w[j];
        out[0] = s;
    }
}

extern "C" void kernel_launch(void* const* d_in, const int* in_sizes, int n_in,
                              void* d_out, int out_size) {
    const float* x     = (const float*)d_in[0];
    const float* topo  = (const float*)d_in[1];
    const float* W1    = (const float*)d_in[2];
    const float* W2    = (const float*)d_in[3];
    const float* c1_w  = (const float*)d_in[4];
    const float* c1_b  = (const float*)d_in[5];
    const float* c2_w  = (const float*)d_in[6];
    const float* c2_b  = (const float*)d_in[7];
    const float* c3_w  = (const float*)d_in[8];
    const float* c3_b  = (const float*)d_in[9];
    const float* c4_w  = (const float*)d_in[10];
    const float* c4_b  = (const float*)d_in[11];
    const float* c5_w  = (const float*)d_in[12];
    const float* c5_b  = (const float*)d_in[13];
    const float* c6_w  = (const float*)d_in[14];
    const float* c6_b  = (const float*)d_in[15];
    const float* out_w = (const float*)d_in[16];
    const float* out_b = (const float*)d_in[17];
    float* out = (float*)d_out;

    k_xmean<<<64, 256>>>(x);
    k_attn<<<64, 128>>>(topo, W1, W2);
    k_y_conv1<<<32, 256>>>(x, c1_w, c1_b);
    k_conv2<<<16, 256>>>(c2_w, c2_b);
    k_tail<<<1, 512>>>(c3_w, c3_b, c4_w, c4_b, c5_w, c5_b, c6_w, c6_b, out_w, out_b, out);
}

// round 6
// speedup vs baseline: 1.4456x; 1.4456x over previous
#include <cuda_runtime.h>
#include <cuda_bf16.h>
#include <math.h>

// ---------------- device scratch (no allocations allowed) ----------------
__device__ float g_xmean[64];
__device__ float g_attn[64 * 64];
__device__ float g_p1[32 * 512];   // after conv1+pool
__device__ float g_p2[16 * 256];   // after conv2+pool

// ---------------- K1: xmean[c] = mean_l x[0,c,l] ----------------
__global__ void k_xmean(const float* __restrict__ x) {
    int c = blockIdx.x;
    int tid = threadIdx.x;
    const float4* xr = (const float4*)(x + c * 1024);
    float4 v = xr[tid];                    // 256 threads * 4 = 1024
    float s = v.x + v.y + v.z + v.w;
    __shared__ float red[8];
    #pragma unroll
    for (int o = 16; o > 0; o >>= 1) s += __shfl_xor_sync(0xffffffffu, s, o);
    if ((tid & 31) == 0) red[tid >> 5] = s;
    __syncthreads();
    if (tid < 8) {
        s = red[tid];
        #pragma unroll
        for (int o = 4; o > 0; o >>= 1) s += __shfl_xor_sync(0xffu, s, o);
        if (tid == 0) g_xmean[c] = s * (1.0f / 1024.0f);
    }
}

// ---------------- K2: per-net MLP -> attn rows ----------------
__global__ void k_attn(const float* __restrict__ topo,
                       const float* __restrict__ W1,
                       const float* __restrict__ W2) {
    __shared__ float att[64];
    __shared__ float hbuf[128];
    __shared__ float wbuf[128 * 65];   // padded: stride 65 / 129 -> conflict-free dots
    int i = blockIdx.x, t = threadIdx.x;

    if (t < 64) att[t] = g_xmean[t] * topo[i * 64 + t];

    // stage W1[i] (128x64) via float4, smem stride 65
    {
        const float4* W1i = (const float4*)(W1 + i * 8192);
        #pragma unroll
        for (int r = 0; r < 16; r++) {
            int v = t + 128 * r;           // 2048 float4
            float4 q = W1i[v];
            int e = v * 4;
            int h = e >> 6, k = e & 63;
            float* d = &wbuf[h * 65 + k];
            d[0] = q.x; d[1] = q.y; d[2] = q.z; d[3] = q.w;
        }
    }
    __syncthreads();

    {
        float s = 0.f;
        const float* wr = &wbuf[t * 65];
        #pragma unroll
        for (int k = 0; k < 64; k++) s += att[k] * wr[k];
        hbuf[t] = fmaxf(s, 0.f);
    }
    __syncthreads();

    // stage W2[i] (64x128) via float4, smem stride 129 (64*129=8256 fits)
    {
        const float4* W2i = (const float4*)(W2 + i * 8192);
        #pragma unroll
        for (int r = 0; r < 16; r++) {
            int v = t + 128 * r;
            float4 q = W2i[v];
            int e = v * 4;
            int o = e >> 7, h = e & 127;
            float* d = &wbuf[o * 129 + h];
            d[0] = q.x; d[1] = q.y; d[2] = q.z; d[3] = q.w;
        }
    }
    __syncthreads();

    if (t < 64) {
        float s = 0.f;
        const float* wr = &wbuf[t * 129];
        #pragma unroll
        for (int h = 0; h < 128; h++) s += hbuf[h] * wr[h];
        g_attn[i * 64 + t] = 1.0f / (1.0f + __expf(-s));
    }
}

// ---------------- K3: y = attn @ x fused with conv1 + relu + pool ----------------
// 32 blocks x 256 threads. Dynamic smem: attn(4096) xs(2304) ys(2304) w(10240).
__global__ void k_y_conv1(const float* __restrict__ x,
                          const float* __restrict__ c1_w,
                          const float* __restrict__ c1_b) {
    extern __shared__ float sm[];
    float* attn_s = sm;             // 64*64
    float* xs     = sm + 4096;      // 64*36
    float* ys     = sm + 4096 + 2304;
    float* wsm    = sm + 4096 + 2304 + 2304;  // 32*64*5 = 10240

    int tile = blockIdx.x, tid = threadIdx.x;
    int l0 = tile * 32 - 2;

    // stage attn (float4) + weights + x slice
    {
        const float4* a4 = (const float4*)g_attn;
        float4* d4 = (float4*)attn_s;
        #pragma unroll
        for (int r = 0; r < 4; r++) d4[tid + 256 * r] = a4[tid + 256 * r];
    }
    for (int j = tid; j < 10240; j += 256) wsm[j] = c1_w[j];
    for (int j = tid; j < 64 * 36; j += 256) {
        int k = j / 36, jj = j - k * 36;
        int gl = l0 + jj;
        xs[j] = ((unsigned)gl < 1024u) ? x[k * 1024 + gl] : 0.f;
    }
    __syncthreads();

    // y tile GEMM: ys[c][j] = sum_k attn[c,k] * xs[k][j]
    for (int idx = tid; idx < 64 * 36; idx += 256) {
        int c = idx / 36, j = idx - c * 36;
        const float* ar = &attn_s[c * 64];
        float s = 0.f;
        #pragma unroll 8
        for (int k = 0; k < 64; k++) s += ar[k] * xs[k * 36 + j];
        ys[idx] = s;
    }
    __syncthreads();

    // conv1 + relu + pool: thread = (oc, 4 prepool positions -> 2 pooled)
    {
        int o = tid >> 3, p2 = tid & 7;     // 32 oc x 8 quad-chunks
        int lb = 4 * p2;                    // local prepool base (halo -2 folded in ys)
        float z0 = c1_b[o], z1 = z0, z2 = z0, z3 = z0;
        const float* wo = &wsm[o * 320];
        for (int c = 0; c < 64; c++) {
            const float* yr = &ys[c * 36 + lb];
            const float* wc = &wo[c * 5];
            #pragma unroll
            for (int dt = 0; dt < 5; dt++) {
                float w = wc[dt];
                z0 += w * yr[dt];
                z1 += w * yr[dt + 1];
                z2 += w * yr[dt + 2];
                z3 += w * yr[dt + 3];
            }
        }
        float v0 = fmaxf(fmaxf(z0, 0.f), fmaxf(z1, 0.f));
        float v1 = fmaxf(fmaxf(z2, 0.f), fmaxf(z3, 0.f));
        int pg = tile * 16 + 2 * p2;
        g_p1[o * 512 + pg]     = v0;
        g_p1[o * 512 + pg + 1] = v1;
    }
}

// ---------------- K4: conv2 + relu + pool (32,512)->(16,256) ----------------
// 32 blocks x 128 threads, all operands staged to smem.
__global__ void k_conv2(const float* __restrict__ c2_w,
                        const float* __restrict__ c2_b) {
    __shared__ float ps[32 * 20];
    __shared__ float ws[16 * 32 * 5];  // 2560
    __shared__ float bs[16];
    int tile = blockIdx.x, tid = threadIdx.x;
    int base = tile * 16 - 2;
    for (int j = tid; j < 640; j += 128) {
        int c = j / 20, m = j - c * 20;
        int g = base + m;
        ps[j] = ((unsigned)g < 512u) ? g_p1[c * 512 + g] : 0.f;
    }
    for (int j = tid; j < 2560; j += 128) ws[j] = c2_w[j];
    if (tid < 16) bs[tid] = c2_b[tid];
    __syncthreads();

    int o = tid >> 3, p = tid & 7;
    float z0 = bs[o], z1 = z0;
    const float* wo = &ws[o * 160];
    for (int c = 0; c < 32; c++) {
        const float* pr = &ps[c * 20 + 2 * p];
        const float* wc = &wo[c * 5];
        #pragma unroll
        for (int dt = 0; dt < 5; dt++) {
            float w = wc[dt];
            z0 += w * pr[dt];
            z1 += w * pr[dt + 1];
        }
    }
    g_p2[o * 256 + tile * 8 + p] = fmaxf(fmaxf(z0, 0.f), fmaxf(z1, 0.f));
}

// ---------------- K5: conv3..conv6 + final linear, one block ----------------
__global__ void k_tail(const float* __restrict__ c3_w, const float* __restrict__ c3_b,
                       const float* __restrict__ c4_w, const float* __restrict__ c4_b,
                       const float* __restrict__ c5_w, const float* __restrict__ c5_b,
                       const float* __restrict__ c6_w, const float* __restrict__ c6_b,
                       const float* __restrict__ out_w, const float* __restrict__ out_b,
                       float* __restrict__ out) {
    __shared__ float s2[16 * 256];
    __shared__ float s3[8 * 128];
    __shared__ float s4[4 * 64];
    __shared__ float s5[2 * 32];
    __shared__ float s6[16];
    __shared__ float wall[640 + 160 + 40 + 10];  // w3|w4|w5|w6 concatenated
    int tid = threadIdx.x;
    float* w3 = wall;
    float* w4 = wall + 640;
    float* w5 = wall + 800;
    float* w6 = wall + 840;

    for (int j = tid; j < 4096; j += 512) s2[j] = g_p2[j];
    // stage all conv weights via one grid-stride loop over the concatenation
    for (int j = tid; j < 850; j += 512) {
        float v;
        if (j < 640)      v = c3_w[j];
        else if (j < 800) v = c4_w[j - 640];
        else if (j < 840) v = c5_w[j - 800];
        else              v = c6_w[j - 840];
        wall[j] = v;
    }
    __syncthreads();

    // conv3: (16,256)->(8,128)
    for (int idx = tid; idx < 1024; idx += 512) {
        int o = idx >> 7, p = idx & 127;
        int l = 2 * p;
        float z0 = c3_b[o], z1 = z0;
        for (int c = 0; c < 16; c++) {
            const float* pr = &s2[c * 256];
            const float* wc = &w3[o * 80 + c * 5];
            #pragma unroll
            for (int dt = 0; dt < 5; dt++) {
                int i0 = l + dt - 2, i1 = i0 + 1;
                float w = wc[dt];
                if ((unsigned)i0 < 256u) z0 += w * pr[i0];
                if ((unsigned)i1 < 256u) z1 += w * pr[i1];
            }
        }
        s3[o * 128 + p] = fmaxf(fmaxf(z0, 0.f), fmaxf(z1, 0.f));
    }
    __syncthreads();

    // conv4: (8,128)->(4,64)
    if (tid < 256) {
        int o = tid >> 6, p = tid & 63;
        int l = 2 * p;
        float z0 = c4_b[o], z1 = z0;
        for (int c = 0; c < 8; c++) {
            const float* pr = &s3[c * 128];
            const float* wc = &w4[o * 40 + c * 5];
            #pragma unroll
            for (int dt = 0; dt < 5; dt++) {
                int i0 = l + dt - 2, i1 = i0 + 1;
                float w = wc[dt];
                if ((unsigned)i0 < 128u) z0 += w * pr[i0];
                if ((unsigned)i1 < 128u) z1 += w * pr[i1];
            }
        }
        s4[o * 64 + p] = fmaxf(fmaxf(z0, 0.f), fmaxf(z1, 0.f));
    }
    __syncthreads();

    // conv5: (4,64)->(2,32)
    if (tid < 64) {
        int o = tid >> 5, p = tid & 31;
        int l = 2 * p;
        float z0 = c5_b[o], z1 = z0;
        for (int c = 0; c < 4; c++) {
            const float* pr = &s4[c * 64];
            const float* wc = &w5[o * 20 + c * 5];
            #pragma unroll
            for (int dt = 0; dt < 5; dt++) {
                int i0 = l + dt - 2, i1 = i0 + 1;
                float w = wc[dt];
                if ((unsigned)i0 < 64u) z0 += w * pr[i0];
                if ((unsigned)i1 < 64u) z1 += w * pr[i1];
            }
        }
        s5[o * 32 + p] = fmaxf(fmaxf(z0, 0.f), fmaxf(z1, 0.f));
    }
    __syncthreads();

    // conv6: (2,32)->(1,16)
    if (tid < 16) {
        int p = tid;
        int l = 2 * p;
        float z0 = c6_b[0], z1 = z0;
        for (int c = 0; c < 2; c++) {
            const float* pr = &s5[c * 32];
            const float* wc = &w6[c * 5];
            #pragma unroll
            for (int dt = 0; dt < 5; dt++) {
                int i0 = l + dt - 2, i1 = i0 + 1;
                float w = wc[dt];
                if ((unsigned)i0 < 32u) z0 += w * pr[i0];
                if ((unsigned)i1 < 32u) z1 += w * pr[i1];
            }
        }
        s6[p] = fmaxf(fmaxf(z0, 0.f), fmaxf(z1, 0.f));
    }
    __syncthreads();

    if (tid == 0) {
        float s = out_b[0];
        #pragma unroll
        for (int j = 0; j < 16; j++) s += s6[j] * out_w[j];
        out[0] = s;
    }
}

extern "C" void kernel_launch(void* const* d_in, const int* in_sizes, int n_in,
                              void* d_out, int out_size) {
    const float* x     = (const float*)d_in[0];
    const float* topo  = (const float*)d_in[1];
    const float* W1    = (const float*)d_in[2];
    const float* W2    = (const float*)d_in[3];
    const float* c1_w  = (const float*)d_in[4];
    const float* c1_b  = (const float*)d_in[5];
    const float* c2_w  = (const float*)d_in[6];
    const float* c2_b  = (const float*)d_in[7];
    const float* c3_w  = (const float*)d_in[8];
    const float* c3_b  = (const float*)d_in[9];
    const float* c4_w  = (const float*)d_in[10];
    const float* c4_b  = (const float*)d_in[11];
    const float* c5_w  = (const float*)d_in[12];
    const float* c5_b  = (const float*)d_in[13];
    const float* c6_w  = (const float*)d_in[14];
    const float* c6_b  = (const float*)d_in[15];
    const float* out_w = (const float*)d_in[16];
    const float* out_b = (const float*)d_in[17];
    float* out = (float*)d_out;

    const int k3_smem = (4096 + 2304 + 2304 + 10240) * 4;   // 75776 B
    cudaFuncSetAttribute(k_y_conv1, cudaFuncAttributeMaxDynamicSharedMemorySize, k3_smem);

    k_xmean<<<64, 256>>>(x);
    k_attn<<<64, 128>>>(topo, W1, W2);
    k_y_conv1<<<32, 256, k3_smem>>>(x, c1_w, c1_b);
    k_conv2<<<32, 128>>>(c2_w, c2_b);
    k_tail<<<1, 512>>>(c3_w, c3_b, c4_w, c4_b, c5_w, c5_b, c6_w, c6_b, out_w, out_b, out);
}